// round 13
// baseline (speedup 1.0000x reference)
#include <cuda_runtime.h>
#include <cuda_bf16.h>
#include <cstdint>

// Problem constants (fixed by the dataset)
#define NNODES 100000
#define FIN    500
#define H1     128
#define H2     64
#define NC     10
#define K1PAD  512
#define EMAX   1700000
#define NB     391          // ceil(NNODES/256)

// ---------------- scratch (device globals; no allocs allowed) ----------------
__device__ __align__(16) float g_dis [NNODES];
__device__ __align__(16) float g_hs1 [NNODES * H1];
__device__ __align__(16) float g_acc1[NNODES * H1];
__device__ __align__(16) float g_hs2 [NNODES * H2];
__device__ __align__(16) __nv_bfloat16 g_W1t_hi[H1 * K1PAD];
__device__ __align__(16) __nv_bfloat16 g_W1t_lo[H1 * K1PAD];
__device__ __align__(16) __nv_bfloat16 g_W2t_hi[H2 * H1];
__device__ __align__(16) __nv_bfloat16 g_W2t_lo[H2 * H1];
__device__ int g_cnt   [NNODES];
__device__ int g_part  [512];
__device__ int g_rowptr[NNODES + 1];
__device__ int g_cursor[NNODES];
__device__ int g_col   [EMAX];
__device__ int g_is64;

__device__ __forceinline__ uint32_t smem_u32(const void* p) {
    uint32_t a;
    asm("{ .reg .u64 t; cvta.to.shared.u64 t, %1; cvt.u32.u64 %0, t; }" : "=r"(a) : "l"(p));
    return a;
}
__device__ __forceinline__ void ldm_x4(uint32_t* r, uint32_t addr) {
    asm volatile("ldmatrix.sync.aligned.m8n8.x4.shared.b16 {%0,%1,%2,%3}, [%4];"
        : "=r"(r[0]), "=r"(r[1]), "=r"(r[2]), "=r"(r[3]) : "r"(addr));
}
__device__ __forceinline__ void mma_bf16(float* c, const uint32_t* a, const uint32_t* b) {
    asm volatile("mma.sync.aligned.m16n8k16.row.col.f32.bf16.bf16.f32 "
        "{%0,%1,%2,%3}, {%4,%5,%6,%7}, {%8,%9}, {%0,%1,%2,%3};"
        : "+f"(c[0]), "+f"(c[1]), "+f"(c[2]), "+f"(c[3])
        : "r"(a[0]), "r"(a[1]), "r"(a[2]), "r"(a[3]), "r"(b[0]), "r"(b[1]));
}
__device__ __forceinline__ void cp16(uint32_t dst, const void* src) {
    asm volatile("cp.async.cg.shared.global [%0], [%1], 16;" :: "r"(dst), "l"(src));
}
__device__ __forceinline__ int eidx(const void* __restrict__ ei, long pos) {
    if (g_is64) return (int)((const long long*)ei)[pos];
    return ((const int*)ei)[pos];
}
// unit-level XOR swizzle: row r (64B = 4 units of 16B), unit u -> byte offset.
__device__ __forceinline__ uint32_t swz(int r, int u) {
    return (uint32_t)(((r * 4 + u) ^ (r & 7)) << 4);
}
// pack top 16 bits of two fp32 words: {b.hi16, a.hi16} in one PRMT
__device__ __forceinline__ unsigned prmt_hi(unsigned a, unsigned b) {
    unsigned r;
    asm("prmt.b32 %0, %1, %2, 0x7632;" : "=r"(r) : "r"(a), "r"(b));
    return r;
}
__device__ __forceinline__ unsigned cvt_bf16x2(float hi, float lo) {
    unsigned r;
    asm("cvt.rn.bf16x2.f32 %0, %1, %2;" : "=r"(r) : "f"(hi), "f"(lo));
    return r;
}

// ---------- launch 1: probe dtype + zero histogram + weight split ------------
__global__ void k_probe_prep(const unsigned* __restrict__ w,
                             const float* __restrict__ W1,
                             const float* __restrict__ W2) {
    if (blockIdx.x == 0) {
        __shared__ unsigned red[256];
        unsigned o = 0;
        for (int i = threadIdx.x; i < 1024; i += 256) o |= w[2 * i + 1];
        red[threadIdx.x] = o;
        __syncthreads();
        for (int s = 128; s; s >>= 1) {
            if (threadIdx.x < s) red[threadIdx.x] |= red[threadIdx.x + s];
            __syncthreads();
        }
        if (threadIdx.x == 0) g_is64 = (red[0] == 0u) ? 1 : 0;
    }
    int i = blockIdx.x * blockDim.x + threadIdx.x;
    int stride = gridDim.x * blockDim.x;
    for (int j = i; j < NNODES; j += stride) g_cnt[j] = 0;
    for (int j = i; j < H1 * K1PAD; j += stride) {
        int n = j / K1PAD, k = j % K1PAD;
        float v = (k < FIN) ? W1[(long)k * H1 + n] : 0.f;
        __nv_bfloat16 h = __float2bfloat16(v);
        g_W1t_hi[j] = h;
        g_W1t_lo[j] = __float2bfloat16(v - __bfloat162float(h));
    }
    for (int j = i; j < H2 * H1; j += stride) {
        int n = j / H1, k = j % H1;
        float v = W2[(long)k * H2 + n];
        __nv_bfloat16 h = __float2bfloat16(v);
        g_W2t_hi[j] = h;
        g_W2t_lo[j] = __float2bfloat16(v - __bfloat162float(h));
    }
}

// ---------- launch 2: degree histogram --------------------------------------
__global__ void k_degree(const void* __restrict__ ei, int E) {
    int i = blockIdx.x * blockDim.x + threadIdx.x;
    if (i < E) atomicAdd(&g_cnt[eidx(ei, (long)E + i)], 1);
}

// ---------- launch 3: block sums + dis = rsqrt(cnt+1) ------------------------
__global__ void k_scanA() {
    int i = blockIdx.x * 256 + threadIdx.x;
    int v = (i < NNODES) ? g_cnt[i] : 0;
    if (i < NNODES) g_dis[i] = rsqrtf((float)v + 1.0f);
    __shared__ int s[256];
    s[threadIdx.x] = v;
    __syncthreads();
    for (int o = 128; o; o >>= 1) {
        if (threadIdx.x < o) s[threadIdx.x] += s[threadIdx.x + o];
        __syncthreads();
    }
    if (threadIdx.x == 0) g_part[blockIdx.x] = s[0];
}

// ---------- side stream: scan the 391 block partials (exclusive) -------------
__global__ void k_scanB() {
    __shared__ int s[512];
    int t = threadIdx.x;
    int v = (t < NB) ? g_part[t] : 0;
    s[t] = v;
    __syncthreads();
    for (int o = 1; o < 512; o <<= 1) {
        int x = (t >= o) ? s[t - o] : 0;
        __syncthreads();
        s[t] += x;
        __syncthreads();
    }
    if (t < NB) g_part[t] = s[t] - v;
}

// ---------- side stream: per-element exclusive scan -> rowptr + cursor -------
__global__ void k_scanC() {
    int b = blockIdx.x, t = threadIdx.x, i = b * 256 + t;
    int v = (i < NNODES) ? g_cnt[i] : 0;
    __shared__ int s[256];
    s[t] = v;
    __syncthreads();
    for (int o = 1; o < 256; o <<= 1) {
        int x = (t >= o) ? s[t - o] : 0;
        __syncthreads();
        s[t] += x;
        __syncthreads();
    }
    int excl = g_part[b] + s[t] - v;
    if (i < NNODES) {
        g_rowptr[i] = excl;
        g_cursor[i] = excl;
        if (i == NNODES - 1) g_rowptr[NNODES] = excl + v;
    }
}

// ---------- side stream: CSR fill (col = src grouped by dst) -----------------
__global__ void k_fill(const void* __restrict__ ei, int E) {
    int i = blockIdx.x * blockDim.x + threadIdx.x;
    if (i < E) {
        int s = eidx(ei, i);
        int d = eidx(ei, (long)E + i);
        int pos = atomicAdd(&g_cursor[d], 1);
        g_col[pos] = s;
    }
}

// ---------------- HMMA split-bf16 GEMM: Cout = dis[row] * (A @ Bt^T) ---------
// BM=64 tiles, NCTA CTAs/SM, double-buffered XOR-swizzled SMEM (64B rows),
// cp.async B, reg-staged A with TRUNCATION hi/lo split (PRMT + 1 cvt per pair).
template <int BM, int BN, int KREAL, int KPAD, int NCTA>
__global__ __launch_bounds__(256, NCTA) void k_mm(
    const float* __restrict__ A, const __nv_bfloat16* __restrict__ Bh,
    const __nv_bfloat16* __restrict__ Bl, float* __restrict__ Cout, int M)
{
    constexpr int BK = 32, C = KPAD / BK;
    static_assert(C % 2 == 0, "C must be even");
    constexpr int WN = BN / 4;
    constexpr int NT = WN / 8;
    constexpr int MT = BM / 32;               // 2
    constexpr int STG = (2 * BM + 2 * BN) * 64;
    constexpr uint32_t oAl = BM * 64;
    constexpr uint32_t oBh = 2 * BM * 64;
    constexpr uint32_t oBl = 2 * BM * 64 + BN * 64;

    extern __shared__ char sm[];
    const uint32_t u0 = smem_u32(sm);

    const int tid = threadIdx.x, wid = tid >> 5, lane = tid & 31;
    const int wm = wid >> 2, wn = wid & 3;
    const int rowBase = blockIdx.x * BM;

    float acc[MT][NT][4];
    #pragma unroll
    for (int m = 0; m < MT; m++)
        #pragma unroll
        for (int n = 0; n < NT; n++)
            #pragma unroll
            for (int j = 0; j < 4; j++) acc[m][n][j] = 0.f;

    float4 aReg[2];
    const int aRow = tid >> 2;        // 4 threads per row
    const int uA   = tid & 3;         // one 16B unit (8 bf16) per thread

    auto loadA = [&](int c) {
        const int k0 = c * BK;
        const int grow = rowBase + aRow;
        #pragma unroll
        for (int i = 0; i < 2; i++) {
            int gcol = k0 + uA * 8 + i * 4;
            float4 v = make_float4(0.f, 0.f, 0.f, 0.f);
            if (grow < M) {
                if (gcol + 4 <= KREAL) {
                    v = *reinterpret_cast<const float4*>(A + (long)grow * KREAL + gcol);
                } else if (gcol < KREAL) {
                    float t[4];
                    #pragma unroll
                    for (int u = 0; u < 4; u++)
                        t[u] = (gcol + u < KREAL) ? A[(long)grow * KREAL + gcol + u] : 0.f;
                    v = make_float4(t[0], t[1], t[2], t[3]);
                }
            }
            aReg[i] = v;
        }
    };
    // truncation split: hi = top-16-bits(v) (exact), lo = v - hi (exact FADD),
    // lo pair -> one cvt.rn.bf16x2. Missing lo*lo product <= 2^-16 relative.
    auto storeA = [&](int s) {
        unsigned h[4], l[4];
        #pragma unroll
        for (int i = 0; i < 2; i++) {
            float4 v = aReg[i];
            unsigned ux = __float_as_uint(v.x), uy = __float_as_uint(v.y);
            unsigned uz = __float_as_uint(v.z), uw = __float_as_uint(v.w);
            h[2 * i + 0] = prmt_hi(ux, uy);
            h[2 * i + 1] = prmt_hi(uz, uw);
            float lx = v.x - __uint_as_float(ux & 0xFFFF0000u);
            float ly = v.y - __uint_as_float(uy & 0xFFFF0000u);
            float lz = v.z - __uint_as_float(uz & 0xFFFF0000u);
            float lw = v.w - __uint_as_float(uw & 0xFFFF0000u);
            l[2 * i + 0] = cvt_bf16x2(ly, lx);
            l[2 * i + 1] = cvt_bf16x2(lw, lz);
        }
        uint32_t off = swz(aRow, uA);
        char* base = sm + s * STG;
        *reinterpret_cast<uint4*>(base + off)       = make_uint4(h[0], h[1], h[2], h[3]);
        *reinterpret_cast<uint4*>(base + oAl + off) = make_uint4(l[0], l[1], l[2], l[3]);
    };
    auto cpB = [&](int c, int s) {
        #pragma unroll
        for (int i = tid; i < BN * 8; i += 256) {
            int mat = (i >= BN * 4) ? 1 : 0;
            int j = i - mat * BN * 4;
            int row = j >> 2, u = j & 3;
            const char* src = (const char*)(mat ? Bl : Bh) +
                              (long)row * (KPAD * 2) + (long)c * 64 + u * 16;
            uint32_t dst = u0 + s * STG + (mat ? oBl : oBh) + swz(row, u);
            cp16(dst, src);
        }
    };

    const int lRow = ((lane >> 3) & 1) * 8 + (lane & 7);
    const int uK   = lane >> 4;       // k-half unit offset

    auto compute = [&](int s) {   // call with literal s -> addresses fold
        const uint32_t base = u0 + s * STG;
        #pragma unroll
        for (int kk = 0; kk < 2; kk++) {
            uint32_t bfH[NT][2], bfL[NT][2];
            #pragma unroll
            for (int np = 0; np < NT / 2; np++) {
                int Rb = wn * WN + np * 16 + lRow;
                uint32_t off = base + oBh + swz(Rb, kk * 2 + uK);
                uint32_t rH[4], rL[4];
                ldm_x4(rH, off);
                ldm_x4(rL, off + (oBl - oBh));
                bfH[np * 2][0] = rH[0]; bfH[np * 2][1] = rH[2];
                bfH[np * 2 + 1][0] = rH[1]; bfH[np * 2 + 1][1] = rH[3];
                bfL[np * 2][0] = rL[0]; bfL[np * 2][1] = rL[2];
                bfL[np * 2 + 1][0] = rL[1]; bfL[np * 2 + 1][1] = rL[3];
            }
            #pragma unroll
            for (int mt = 0; mt < MT; mt++) {
                int Ra = wm * (MT * 16) + mt * 16 + lRow;
                uint32_t off = base + swz(Ra, kk * 2 + uK);
                uint32_t afH[4], afL[4];
                ldm_x4(afH, off);
                ldm_x4(afL, off + oAl);
                #pragma unroll
                for (int nt = 0; nt < NT; nt++) {
                    mma_bf16(acc[mt][nt], afH, bfH[nt]);
                    mma_bf16(acc[mt][nt], afH, bfL[nt]);
                    mma_bf16(acc[mt][nt], afL, bfH[nt]);
                }
            }
        }
    };

    // prologue: chunk 0 into stage 0
    loadA(0);
    cpB(0, 0);
    storeA(0);
    asm volatile("cp.async.commit_group;");
    asm volatile("cp.async.wait_group 0;");
    __syncthreads();

    // main loop unrolled x2: stage indices are literals
    #pragma unroll 1
    for (int c = 0; c < C; c += 2) {
        const bool has1 = (c + 1 < C);
        const bool has2 = (c + 2 < C);
        if (has1) {
            loadA(c + 1);
            cpB(c + 1, 1);
            asm volatile("cp.async.commit_group;");
        }
        compute(0);
        if (has1) {
            storeA(1);
            asm volatile("cp.async.wait_group 0;");
            __syncthreads();
        }
        if (has2) {
            loadA(c + 2);
            cpB(c + 2, 0);
            asm volatile("cp.async.commit_group;");
        }
        if (has1) compute(1);
        if (has2) {
            storeA(0);
            asm volatile("cp.async.wait_group 0;");
            __syncthreads();
        }
    }

    #pragma unroll
    for (int mt = 0; mt < MT; mt++) {
        int r0 = rowBase + wm * (MT * 16) + mt * 16 + (lane >> 2);
        int r1 = r0 + 8;
        float s0 = (r0 < M) ? g_dis[r0] : 0.f;
        float s1 = (r1 < M) ? g_dis[r1] : 0.f;
        #pragma unroll
        for (int nt = 0; nt < NT; nt++) {
            int col = wn * WN + nt * 8 + 2 * (lane & 3);
            if (r0 < M) {
                float2 v = make_float2(acc[mt][nt][0] * s0, acc[mt][nt][1] * s0);
                *reinterpret_cast<float2*>(Cout + (long)r0 * BN + col) = v;
            }
            if (r1 < M) {
                float2 v = make_float2(acc[mt][nt][2] * s1, acc[mt][nt][3] * s1);
                *reinterpret_cast<float2*>(Cout + (long)r1 * BN + col) = v;
            }
        }
    }
}

// ---------- CSR aggregation layer1 + finish: warp = node, lane = float4 ------
__global__ __launch_bounds__(256) void k_agg1(const float* __restrict__ b1) {
    const int wid = threadIdx.x >> 5, lane = threadIdx.x & 31;
    const int n = blockIdx.x * 8 + wid;
    if (n >= NNODES) return;
    const int s0 = g_rowptr[n], e0 = g_rowptr[n + 1];
    const float4* __restrict__ hs = reinterpret_cast<const float4*>(g_hs1);
    float4 a0 = make_float4(0.f, 0.f, 0.f, 0.f), a1 = a0, a2 = a0, a3 = a0;
    int i = s0;
    for (; i + 4 <= e0; i += 4) {
        int c0 = g_col[i], c1 = g_col[i + 1], c2 = g_col[i + 2], c3 = g_col[i + 3];
        float4 v0 = hs[(long)c0 * 32 + lane];
        float4 v1 = hs[(long)c1 * 32 + lane];
        float4 v2 = hs[(long)c2 * 32 + lane];
        float4 v3 = hs[(long)c3 * 32 + lane];
        a0.x += v0.x; a0.y += v0.y; a0.z += v0.z; a0.w += v0.w;
        a1.x += v1.x; a1.y += v1.y; a1.z += v1.z; a1.w += v1.w;
        a2.x += v2.x; a2.y += v2.y; a2.z += v2.z; a2.w += v2.w;
        a3.x += v3.x; a3.y += v3.y; a3.z += v3.z; a3.w += v3.w;
    }
    for (; i < e0; i++) {
        float4 v = hs[(long)g_col[i] * 32 + lane];
        a0.x += v.x; a0.y += v.y; a0.z += v.z; a0.w += v.w;
    }
    float4 a = make_float4((a0.x + a1.x) + (a2.x + a3.x), (a0.y + a1.y) + (a2.y + a3.y),
                           (a0.z + a1.z) + (a2.z + a3.z), (a0.w + a1.w) + (a2.w + a3.w));
    float s = g_dis[n];
    float4 self = hs[(long)n * 32 + lane];
    float4 bb = __ldg(reinterpret_cast<const float4*>(b1) + lane);
    float4 r;
    r.x = fmaxf(s * (a.x + self.x) + bb.x, 0.f);
    r.y = fmaxf(s * (a.y + self.y) + bb.y, 0.f);
    r.z = fmaxf(s * (a.z + self.z) + bb.z, 0.f);
    r.w = fmaxf(s * (a.w + self.w) + bb.w, 0.f);
    reinterpret_cast<float4*>(g_acc1)[(long)n * 32 + lane] = r;
}

// ---------- CSR aggregation layer2 + finish + classifier: warp = node --------
__global__ __launch_bounds__(256) void k_agg2(
    const float* __restrict__ b2, const float* __restrict__ Wc,
    const float* __restrict__ bc, float* __restrict__ out) {
    const int wid = threadIdx.x >> 5, lane = threadIdx.x & 31;
    const int n = blockIdx.x * 8 + wid;
    if (n >= NNODES) return;
    const int s0 = g_rowptr[n], e0 = g_rowptr[n + 1];
    const float2* __restrict__ hs = reinterpret_cast<const float2*>(g_hs2);
    float2 a0 = make_float2(0.f, 0.f), a1 = a0, a2 = a0, a3 = a0;
    int i = s0;
    for (; i + 4 <= e0; i += 4) {
        int c0 = g_col[i], c1 = g_col[i + 1], c2 = g_col[i + 2], c3 = g_col[i + 3];
        float2 v0 = hs[(long)c0 * 32 + lane];
        float2 v1 = hs[(long)c1 * 32 + lane];
        float2 v2 = hs[(long)c2 * 32 + lane];
        float2 v3 = hs[(long)c3 * 32 + lane];
        a0.x += v0.x; a0.y += v0.y;
        a1.x += v1.x; a1.y += v1.y;
        a2.x += v2.x; a2.y += v2.y;
        a3.x += v3.x; a3.y += v3.y;
    }
    for (; i < e0; i++) {
        float2 v = hs[(long)g_col[i] * 32 + lane];
        a0.x += v.x; a0.y += v.y;
    }
    float ax = (a0.x + a1.x) + (a2.x + a3.x);
    float ay = (a0.y + a1.y) + (a2.y + a3.y);
    float s = g_dis[n];
    float2 self = hs[(long)n * 32 + lane];
    float2 bb = __ldg(reinterpret_cast<const float2*>(b2) + lane);
    float hx = fmaxf(s * (ax + self.x) + bb.x, 0.f);
    float hy = fmaxf(s * (ay + self.y) + bb.y, 0.f);

    float p[NC];
    #pragma unroll
    for (int c = 0; c < NC; c++) {
        float v = hx * __ldg(&Wc[(2 * lane) * NC + c]) + hy * __ldg(&Wc[(2 * lane + 1) * NC + c]);
        #pragma unroll
        for (int o = 16; o; o >>= 1) v += __shfl_xor_sync(0xFFFFFFFFu, v, o);
        p[c] = v;
    }
    if (lane < NC) out[(long)n * NC + lane] = p[lane] + __ldg(&bc[lane]);
}

// ---------------- launch ------------------------------------------------------
extern "C" void kernel_launch(void* const* d_in, const int* in_sizes, int n_in,
                              void* d_out, int out_size)
{
    const float* x  = (const float*)d_in[0];
    const void*  ei = d_in[1];
    const float* W1 = (const float*)d_in[2];
    const float* b1 = (const float*)d_in[3];
    const float* W2 = (const float*)d_in[4];
    const float* b2 = (const float*)d_in[5];
    const float* Wc = (const float*)d_in[6];
    const float* bc = (const float*)d_in[7];
    float* out = (float*)d_out;

    const int E = in_sizes[1] / 2;

    constexpr int SMEM1 = 2 * (2 * 64 + 2 * H1) * 64;  // 49152
    constexpr int SMEM2 = 2 * (2 * 64 + 2 * H2) * 64;  // 32768

    static float *p_hs1 = nullptr, *p_acc1 = nullptr, *p_hs2 = nullptr;
    static __nv_bfloat16 *p_w1h = nullptr, *p_w1l = nullptr, *p_w2h = nullptr, *p_w2l = nullptr;
    static cudaStream_t sideStream = nullptr;
    static cudaEvent_t evFork = nullptr, evJoin = nullptr;
    if (!p_hs1) {
        cudaGetSymbolAddress((void**)&p_hs1,  g_hs1);
        cudaGetSymbolAddress((void**)&p_acc1, g_acc1);
        cudaGetSymbolAddress((void**)&p_hs2,  g_hs2);
        cudaGetSymbolAddress((void**)&p_w1h,  g_W1t_hi);
        cudaGetSymbolAddress((void**)&p_w1l,  g_W1t_lo);
        cudaGetSymbolAddress((void**)&p_w2h,  g_W2t_hi);
        cudaGetSymbolAddress((void**)&p_w2l,  g_W2t_lo);
        cudaFuncSetAttribute(k_mm<64, H1, FIN, K1PAD, 3>,
                             cudaFuncAttributeMaxDynamicSharedMemorySize, SMEM1);
        cudaFuncSetAttribute(k_mm<64, H2, H1, H1, 4>,
                             cudaFuncAttributeMaxDynamicSharedMemorySize, SMEM2);
        cudaStreamCreateWithFlags(&sideStream, cudaStreamNonBlocking);
        cudaEventCreateWithFlags(&evFork, cudaEventDisableTiming);
        cudaEventCreateWithFlags(&evJoin, cudaEventDisableTiming);
    }

    const int grid = (NNODES + 63) / 64;   // 1563
    const int gridAgg = (NNODES + 7) / 8;  // 12500

    // 1: probe + zero hist + weight split
    k_probe_prep<<<512, 256>>>((const unsigned*)ei, W1, W2);
    // 2: degree histogram
    k_degree<<<(E + 255) / 256, 256>>>(ei, E);
    // 3: block sums + dis
    k_scanA<<<NB, 256>>>();
    // fork: CSR build runs on side stream, concurrent with layer-1 GEMM
    cudaEventRecord(evFork, 0);
    // 4: layer-1 GEMM on main stream (ncu -s 5 -c 1 window)
    k_mm<64, H1, FIN, K1PAD, 3><<<grid, 256, SMEM1>>>(x, p_w1h, p_w1l, p_hs1, NNODES);
    cudaStreamWaitEvent(sideStream, evFork, 0);
    k_scanB<<<1, 512, 0, sideStream>>>();
    k_scanC<<<NB, 256, 0, sideStream>>>();
    k_fill<<<(E + 255) / 256, 256, 0, sideStream>>>(ei, E);
    cudaEventRecord(evJoin, sideStream);
    cudaStreamWaitEvent(0, evJoin, 0);
    // 8: layer-1 aggregation + relu (writes h into acc1)
    k_agg1<<<gridAgg, 256>>>(b1);
    // 9: layer-2 GEMM
    k_mm<64, H2, H1, H1, 4><<<grid, 256, SMEM2>>>(p_acc1, p_w2h, p_w2l, p_hs2, NNODES);
    // 10: layer-2 aggregation + relu + classifier
    k_agg2<<<gridAgg, 256>>>(b2, Wc, bc, out);
}

// round 14
// speedup vs baseline: 1.0474x; 1.0474x over previous
#include <cuda_runtime.h>
#include <cuda_bf16.h>
#include <cuda_fp16.h>
#include <cstdint>

// Problem constants (fixed by the dataset)
#define NNODES 100000
#define FIN    500
#define H1     128
#define H2     64
#define NC     10
#define K1PAD  512
#define EMAX   1700000
#define NB     391          // ceil(NNODES/256)

// ---------------- scratch (device globals; no allocs allowed) ----------------
__device__ __align__(16) float  g_dis [NNODES];
__device__ __align__(16) __half g_hs1 [NNODES * H1];   // dis*(x@W1), fp16
__device__ __align__(16) float  g_acc1[NNODES * H1];   // layer-1 output h (fp32)
__device__ __align__(16) __half g_hs2 [NNODES * H2];   // dis*(h@W2), fp16
__device__ __align__(16) __nv_bfloat16 g_W1t_hi[H1 * K1PAD];
__device__ __align__(16) __nv_bfloat16 g_W1t_lo[H1 * K1PAD];
__device__ __align__(16) __nv_bfloat16 g_W2t_hi[H2 * H1];
__device__ __align__(16) __nv_bfloat16 g_W2t_lo[H2 * H1];
__device__ int g_cnt   [NNODES];
__device__ int g_part  [512];
__device__ int g_rowptr[NNODES + 1];
__device__ int g_cursor[NNODES];
__device__ int g_col   [EMAX];
__device__ int g_is64;

__device__ __forceinline__ uint32_t smem_u32(const void* p) {
    uint32_t a;
    asm("{ .reg .u64 t; cvta.to.shared.u64 t, %1; cvt.u32.u64 %0, t; }" : "=r"(a) : "l"(p));
    return a;
}
__device__ __forceinline__ void ldm_x4(uint32_t* r, uint32_t addr) {
    asm volatile("ldmatrix.sync.aligned.m8n8.x4.shared.b16 {%0,%1,%2,%3}, [%4];"
        : "=r"(r[0]), "=r"(r[1]), "=r"(r[2]), "=r"(r[3]) : "r"(addr));
}
__device__ __forceinline__ void mma_bf16(float* c, const uint32_t* a, const uint32_t* b) {
    asm volatile("mma.sync.aligned.m16n8k16.row.col.f32.bf16.bf16.f32 "
        "{%0,%1,%2,%3}, {%4,%5,%6,%7}, {%8,%9}, {%0,%1,%2,%3};"
        : "+f"(c[0]), "+f"(c[1]), "+f"(c[2]), "+f"(c[3])
        : "r"(a[0]), "r"(a[1]), "r"(a[2]), "r"(a[3]), "r"(b[0]), "r"(b[1]));
}
__device__ __forceinline__ void cp16(uint32_t dst, const void* src) {
    asm volatile("cp.async.cg.shared.global [%0], [%1], 16;" :: "r"(dst), "l"(src));
}
__device__ __forceinline__ int eidx(const void* __restrict__ ei, long pos) {
    if (g_is64) return (int)((const long long*)ei)[pos];
    return ((const int*)ei)[pos];
}
// unit-level XOR swizzle: row r (64B = 4 units of 16B), unit u -> byte offset.
__device__ __forceinline__ uint32_t swz(int r, int u) {
    return (uint32_t)(((r * 4 + u) ^ (r & 7)) << 4);
}
// pack top 16 bits of two fp32 words: {b.hi16, a.hi16} in one PRMT
__device__ __forceinline__ unsigned prmt_hi(unsigned a, unsigned b) {
    unsigned r;
    asm("prmt.b32 %0, %1, %2, 0x7632;" : "=r"(r) : "r"(a), "r"(b));
    return r;
}
__device__ __forceinline__ unsigned cvt_bf16x2(float hi, float lo) {
    unsigned r;
    asm("cvt.rn.bf16x2.f32 %0, %1, %2;" : "=r"(r) : "f"(hi), "f"(lo));
    return r;
}
// unpack 4 fp16 (uint2) -> float4
__device__ __forceinline__ float4 h2f4(uint2 v) {
    __half2 a = *reinterpret_cast<__half2*>(&v.x);
    __half2 b = *reinterpret_cast<__half2*>(&v.y);
    float2 fa = __half22float2(a), fb = __half22float2(b);
    return make_float4(fa.x, fa.y, fb.x, fb.y);
}
__device__ __forceinline__ float2 h2f2(unsigned v) {
    __half2 a = *reinterpret_cast<__half2*>(&v);
    return __half22float2(a);
}

// ---------- launch 1: probe dtype + zero histogram + weight split ------------
__global__ void k_probe_prep(const unsigned* __restrict__ w,
                             const float* __restrict__ W1,
                             const float* __restrict__ W2) {
    if (blockIdx.x == 0) {
        __shared__ unsigned red[256];
        unsigned o = 0;
        for (int i = threadIdx.x; i < 1024; i += 256) o |= w[2 * i + 1];
        red[threadIdx.x] = o;
        __syncthreads();
        for (int s = 128; s; s >>= 1) {
            if (threadIdx.x < s) red[threadIdx.x] |= red[threadIdx.x + s];
            __syncthreads();
        }
        if (threadIdx.x == 0) g_is64 = (red[0] == 0u) ? 1 : 0;
    }
    int i = blockIdx.x * blockDim.x + threadIdx.x;
    int stride = gridDim.x * blockDim.x;
    for (int j = i; j < NNODES; j += stride) g_cnt[j] = 0;
    for (int j = i; j < H1 * K1PAD; j += stride) {
        int n = j / K1PAD, k = j % K1PAD;
        float v = (k < FIN) ? W1[(long)k * H1 + n] : 0.f;
        __nv_bfloat16 h = __float2bfloat16(v);
        g_W1t_hi[j] = h;
        g_W1t_lo[j] = __float2bfloat16(v - __bfloat162float(h));
    }
    for (int j = i; j < H2 * H1; j += stride) {
        int n = j / H1, k = j % H1;
        float v = W2[(long)k * H2 + n];
        __nv_bfloat16 h = __float2bfloat16(v);
        g_W2t_hi[j] = h;
        g_W2t_lo[j] = __float2bfloat16(v - __bfloat162float(h));
    }
}

// ---------- launch 2: degree histogram --------------------------------------
__global__ void k_degree(const void* __restrict__ ei, int E) {
    int i = blockIdx.x * blockDim.x + threadIdx.x;
    if (i < E) atomicAdd(&g_cnt[eidx(ei, (long)E + i)], 1);
}

// ---------- launch 3: block sums + dis = rsqrt(cnt+1) ------------------------
__global__ void k_scanA() {
    int i = blockIdx.x * 256 + threadIdx.x;
    int v = (i < NNODES) ? g_cnt[i] : 0;
    if (i < NNODES) g_dis[i] = rsqrtf((float)v + 1.0f);
    __shared__ int s[256];
    s[threadIdx.x] = v;
    __syncthreads();
    for (int o = 128; o; o >>= 1) {
        if (threadIdx.x < o) s[threadIdx.x] += s[threadIdx.x + o];
        __syncthreads();
    }
    if (threadIdx.x == 0) g_part[blockIdx.x] = s[0];
}

// ---------- side stream: scan the 391 block partials (exclusive) -------------
__global__ void k_scanB() {
    __shared__ int s[512];
    int t = threadIdx.x;
    int v = (t < NB) ? g_part[t] : 0;
    s[t] = v;
    __syncthreads();
    for (int o = 1; o < 512; o <<= 1) {
        int x = (t >= o) ? s[t - o] : 0;
        __syncthreads();
        s[t] += x;
        __syncthreads();
    }
    if (t < NB) g_part[t] = s[t] - v;
}

// ---------- side stream: per-element exclusive scan -> rowptr + cursor -------
__global__ void k_scanC() {
    int b = blockIdx.x, t = threadIdx.x, i = b * 256 + t;
    int v = (i < NNODES) ? g_cnt[i] : 0;
    __shared__ int s[256];
    s[t] = v;
    __syncthreads();
    for (int o = 1; o < 256; o <<= 1) {
        int x = (t >= o) ? s[t - o] : 0;
        __syncthreads();
        s[t] += x;
        __syncthreads();
    }
    int excl = g_part[b] + s[t] - v;
    if (i < NNODES) {
        g_rowptr[i] = excl;
        g_cursor[i] = excl;
        if (i == NNODES - 1) g_rowptr[NNODES] = excl + v;
    }
}

// ---------- side stream: CSR fill (col = src grouped by dst) -----------------
__global__ void k_fill(const void* __restrict__ ei, int E) {
    int i = blockIdx.x * blockDim.x + threadIdx.x;
    if (i < E) {
        int s = eidx(ei, i);
        int d = eidx(ei, (long)E + i);
        int pos = atomicAdd(&g_cursor[d], 1);
        g_col[pos] = s;
    }
}

// ---------------- HMMA split-bf16 GEMM: Cout = dis[row] * (A @ Bt^T) ---------
// BM=64 tiles, NCTA CTAs/SM, double-buffered XOR-swizzled SMEM (64B rows),
// cp.async B, reg-staged A, truncation hi/lo split. OUT16: fp16 output.
template <int BM, int BN, int KREAL, int KPAD, int NCTA, int OUT16>
__global__ __launch_bounds__(256, NCTA) void k_mm(
    const float* __restrict__ A, const __nv_bfloat16* __restrict__ Bh,
    const __nv_bfloat16* __restrict__ Bl, void* __restrict__ Cout, int M)
{
    constexpr int BK = 32, C = KPAD / BK;
    static_assert(C % 2 == 0, "C must be even");
    constexpr int WN = BN / 4;
    constexpr int NT = WN / 8;
    constexpr int MT = BM / 32;               // 2
    constexpr int STG = (2 * BM + 2 * BN) * 64;
    constexpr uint32_t oAl = BM * 64;
    constexpr uint32_t oBh = 2 * BM * 64;
    constexpr uint32_t oBl = 2 * BM * 64 + BN * 64;

    extern __shared__ char sm[];
    const uint32_t u0 = smem_u32(sm);

    const int tid = threadIdx.x, wid = tid >> 5, lane = tid & 31;
    const int wm = wid >> 2, wn = wid & 3;
    const int rowBase = blockIdx.x * BM;

    float acc[MT][NT][4];
    #pragma unroll
    for (int m = 0; m < MT; m++)
        #pragma unroll
        for (int n = 0; n < NT; n++)
            #pragma unroll
            for (int j = 0; j < 4; j++) acc[m][n][j] = 0.f;

    float4 aReg[2];
    const int aRow = tid >> 2;        // 4 threads per row
    const int uA   = tid & 3;         // one 16B unit (8 bf16) per thread

    auto loadA = [&](int c) {
        const int k0 = c * BK;
        const int grow = rowBase + aRow;
        #pragma unroll
        for (int i = 0; i < 2; i++) {
            int gcol = k0 + uA * 8 + i * 4;
            float4 v = make_float4(0.f, 0.f, 0.f, 0.f);
            if (grow < M) {
                if (gcol + 4 <= KREAL) {
                    v = *reinterpret_cast<const float4*>(A + (long)grow * KREAL + gcol);
                } else if (gcol < KREAL) {
                    float t[4];
                    #pragma unroll
                    for (int u = 0; u < 4; u++)
                        t[u] = (gcol + u < KREAL) ? A[(long)grow * KREAL + gcol + u] : 0.f;
                    v = make_float4(t[0], t[1], t[2], t[3]);
                }
            }
            aReg[i] = v;
        }
    };
    // truncation split: hi = top-16-bits(v) (exact), lo = v - hi (exact FADD),
    // lo pair -> one cvt.rn.bf16x2. Missing lo*lo product <= 2^-16 relative.
    auto storeA = [&](int s) {
        unsigned h[4], l[4];
        #pragma unroll
        for (int i = 0; i < 2; i++) {
            float4 v = aReg[i];
            unsigned ux = __float_as_uint(v.x), uy = __float_as_uint(v.y);
            unsigned uz = __float_as_uint(v.z), uw = __float_as_uint(v.w);
            h[2 * i + 0] = prmt_hi(ux, uy);
            h[2 * i + 1] = prmt_hi(uz, uw);
            float lx = v.x - __uint_as_float(ux & 0xFFFF0000u);
            float ly = v.y - __uint_as_float(uy & 0xFFFF0000u);
            float lz = v.z - __uint_as_float(uz & 0xFFFF0000u);
            float lw = v.w - __uint_as_float(uw & 0xFFFF0000u);
            l[2 * i + 0] = cvt_bf16x2(ly, lx);
            l[2 * i + 1] = cvt_bf16x2(lw, lz);
        }
        uint32_t off = swz(aRow, uA);
        char* base = sm + s * STG;
        *reinterpret_cast<uint4*>(base + off)       = make_uint4(h[0], h[1], h[2], h[3]);
        *reinterpret_cast<uint4*>(base + oAl + off) = make_uint4(l[0], l[1], l[2], l[3]);
    };
    auto cpB = [&](int c, int s) {
        #pragma unroll
        for (int i = tid; i < BN * 8; i += 256) {
            int mat = (i >= BN * 4) ? 1 : 0;
            int j = i - mat * BN * 4;
            int row = j >> 2, u = j & 3;
            const char* src = (const char*)(mat ? Bl : Bh) +
                              (long)row * (KPAD * 2) + (long)c * 64 + u * 16;
            uint32_t dst = u0 + s * STG + (mat ? oBl : oBh) + swz(row, u);
            cp16(dst, src);
        }
    };

    const int lRow = ((lane >> 3) & 1) * 8 + (lane & 7);
    const int uK   = lane >> 4;       // k-half unit offset

    auto compute = [&](int s) {   // call with literal s -> addresses fold
        const uint32_t base = u0 + s * STG;
        #pragma unroll
        for (int kk = 0; kk < 2; kk++) {
            uint32_t bfH[NT][2], bfL[NT][2];
            #pragma unroll
            for (int np = 0; np < NT / 2; np++) {
                int Rb = wn * WN + np * 16 + lRow;
                uint32_t off = base + oBh + swz(Rb, kk * 2 + uK);
                uint32_t rH[4], rL[4];
                ldm_x4(rH, off);
                ldm_x4(rL, off + (oBl - oBh));
                bfH[np * 2][0] = rH[0]; bfH[np * 2][1] = rH[2];
                bfH[np * 2 + 1][0] = rH[1]; bfH[np * 2 + 1][1] = rH[3];
                bfL[np * 2][0] = rL[0]; bfL[np * 2][1] = rL[2];
                bfL[np * 2 + 1][0] = rL[1]; bfL[np * 2 + 1][1] = rL[3];
            }
            #pragma unroll
            for (int mt = 0; mt < MT; mt++) {
                int Ra = wm * (MT * 16) + mt * 16 + lRow;
                uint32_t off = base + swz(Ra, kk * 2 + uK);
                uint32_t afH[4], afL[4];
                ldm_x4(afH, off);
                ldm_x4(afL, off + oAl);
                #pragma unroll
                for (int nt = 0; nt < NT; nt++) {
                    mma_bf16(acc[mt][nt], afH, bfH[nt]);
                    mma_bf16(acc[mt][nt], afH, bfL[nt]);
                    mma_bf16(acc[mt][nt], afL, bfH[nt]);
                }
            }
        }
    };

    // prologue: chunk 0 into stage 0
    loadA(0);
    cpB(0, 0);
    storeA(0);
    asm volatile("cp.async.commit_group;");
    asm volatile("cp.async.wait_group 0;");
    __syncthreads();

    // main loop unrolled x2: stage indices are literals
    #pragma unroll 1
    for (int c = 0; c < C; c += 2) {
        const bool has1 = (c + 1 < C);
        const bool has2 = (c + 2 < C);
        if (has1) {
            loadA(c + 1);
            cpB(c + 1, 1);
            asm volatile("cp.async.commit_group;");
        }
        compute(0);
        if (has1) {
            storeA(1);
            asm volatile("cp.async.wait_group 0;");
            __syncthreads();
        }
        if (has2) {
            loadA(c + 2);
            cpB(c + 2, 0);
            asm volatile("cp.async.commit_group;");
        }
        if (has1) compute(1);
        if (has2) {
            storeA(0);
            asm volatile("cp.async.wait_group 0;");
            __syncthreads();
        }
    }

    // epilogue: scale rows by g_dis, store fp16 (OUT16) or fp32
    auto store2 = [&](int r, int col, float v0, float v1) {
        if (OUT16) {
            __half2 hv = __floats2half2_rn(v0, v1);
            *reinterpret_cast<__half2*>((__half*)Cout + (long)r * BN + col) = hv;
        } else {
            *reinterpret_cast<float2*>((float*)Cout + (long)r * BN + col) =
                make_float2(v0, v1);
        }
    };
    #pragma unroll
    for (int mt = 0; mt < MT; mt++) {
        int r0 = rowBase + wm * (MT * 16) + mt * 16 + (lane >> 2);
        int r1 = r0 + 8;
        float s0 = (r0 < M) ? g_dis[r0] : 0.f;
        float s1 = (r1 < M) ? g_dis[r1] : 0.f;
        #pragma unroll
        for (int nt = 0; nt < NT; nt++) {
            int col = wn * WN + nt * 8 + 2 * (lane & 3);
            if (r0 < M) store2(r0, col, acc[mt][nt][0] * s0, acc[mt][nt][1] * s0);
            if (r1 < M) store2(r1, col, acc[mt][nt][2] * s1, acc[mt][nt][3] * s1);
        }
    }
}

// ---------- CSR aggregation layer1 + finish: warp = node, lane = 4 fp16 ------
__global__ __launch_bounds__(256) void k_agg1(const float* __restrict__ b1) {
    const int wid = threadIdx.x >> 5, lane = threadIdx.x & 31;
    const int n = blockIdx.x * 8 + wid;
    if (n >= NNODES) return;
    const int s0 = g_rowptr[n], e0 = g_rowptr[n + 1];
    const uint2* __restrict__ hs = reinterpret_cast<const uint2*>(g_hs1);  // 32 uint2/row
    float4 a0 = make_float4(0.f, 0.f, 0.f, 0.f), a1 = a0, a2 = a0, a3 = a0;
    int i = s0;
    for (; i + 4 <= e0; i += 4) {
        int c0 = g_col[i], c1 = g_col[i + 1], c2 = g_col[i + 2], c3 = g_col[i + 3];
        float4 v0 = h2f4(hs[(long)c0 * 32 + lane]);
        float4 v1 = h2f4(hs[(long)c1 * 32 + lane]);
        float4 v2 = h2f4(hs[(long)c2 * 32 + lane]);
        float4 v3 = h2f4(hs[(long)c3 * 32 + lane]);
        a0.x += v0.x; a0.y += v0.y; a0.z += v0.z; a0.w += v0.w;
        a1.x += v1.x; a1.y += v1.y; a1.z += v1.z; a1.w += v1.w;
        a2.x += v2.x; a2.y += v2.y; a2.z += v2.z; a2.w += v2.w;
        a3.x += v3.x; a3.y += v3.y; a3.z += v3.z; a3.w += v3.w;
    }
    for (; i < e0; i++) {
        float4 v = h2f4(hs[(long)g_col[i] * 32 + lane]);
        a0.x += v.x; a0.y += v.y; a0.z += v.z; a0.w += v.w;
    }
    float4 a = make_float4((a0.x + a1.x) + (a2.x + a3.x), (a0.y + a1.y) + (a2.y + a3.y),
                           (a0.z + a1.z) + (a2.z + a3.z), (a0.w + a1.w) + (a2.w + a3.w));
    float s = g_dis[n];
    float4 self = h2f4(hs[(long)n * 32 + lane]);
    float4 bb = __ldg(reinterpret_cast<const float4*>(b1) + lane);
    float4 r;
    r.x = fmaxf(s * (a.x + self.x) + bb.x, 0.f);
    r.y = fmaxf(s * (a.y + self.y) + bb.y, 0.f);
    r.z = fmaxf(s * (a.z + self.z) + bb.z, 0.f);
    r.w = fmaxf(s * (a.w + self.w) + bb.w, 0.f);
    reinterpret_cast<float4*>(g_acc1)[(long)n * 32 + lane] = r;
}

// ---------- CSR aggregation layer2 + finish + classifier: warp = node --------
__global__ __launch_bounds__(256) void k_agg2(
    const float* __restrict__ b2, const float* __restrict__ Wc,
    const float* __restrict__ bc, float* __restrict__ out) {
    const int wid = threadIdx.x >> 5, lane = threadIdx.x & 31;
    const int n = blockIdx.x * 8 + wid;
    if (n >= NNODES) return;
    const int s0 = g_rowptr[n], e0 = g_rowptr[n + 1];
    const unsigned* __restrict__ hs = reinterpret_cast<const unsigned*>(g_hs2); // 32 half2/row
    float2 a0 = make_float2(0.f, 0.f), a1 = a0, a2 = a0, a3 = a0;
    int i = s0;
    for (; i + 4 <= e0; i += 4) {
        int c0 = g_col[i], c1 = g_col[i + 1], c2 = g_col[i + 2], c3 = g_col[i + 3];
        float2 v0 = h2f2(hs[(long)c0 * 32 + lane]);
        float2 v1 = h2f2(hs[(long)c1 * 32 + lane]);
        float2 v2 = h2f2(hs[(long)c2 * 32 + lane]);
        float2 v3 = h2f2(hs[(long)c3 * 32 + lane]);
        a0.x += v0.x; a0.y += v0.y;
        a1.x += v1.x; a1.y += v1.y;
        a2.x += v2.x; a2.y += v2.y;
        a3.x += v3.x; a3.y += v3.y;
    }
    for (; i < e0; i++) {
        float2 v = h2f2(hs[(long)g_col[i] * 32 + lane]);
        a0.x += v.x; a0.y += v.y;
    }
    float ax = (a0.x + a1.x) + (a2.x + a3.x);
    float ay = (a0.y + a1.y) + (a2.y + a3.y);
    float s = g_dis[n];
    float2 self = h2f2(hs[(long)n * 32 + lane]);
    float2 bb = __ldg(reinterpret_cast<const float2*>(b2) + lane);
    float hx = fmaxf(s * (ax + self.x) + bb.x, 0.f);
    float hy = fmaxf(s * (ay + self.y) + bb.y, 0.f);

    float p[NC];
    #pragma unroll
    for (int c = 0; c < NC; c++) {
        float v = hx * __ldg(&Wc[(2 * lane) * NC + c]) + hy * __ldg(&Wc[(2 * lane + 1) * NC + c]);
        #pragma unroll
        for (int o = 16; o; o >>= 1) v += __shfl_xor_sync(0xFFFFFFFFu, v, o);
        p[c] = v;
    }
    if (lane < NC) out[(long)n * NC + lane] = p[lane] + __ldg(&bc[lane]);
}

// ---------------- launch ------------------------------------------------------
extern "C" void kernel_launch(void* const* d_in, const int* in_sizes, int n_in,
                              void* d_out, int out_size)
{
    const float* x  = (const float*)d_in[0];
    const void*  ei = d_in[1];
    const float* W1 = (const float*)d_in[2];
    const float* b1 = (const float*)d_in[3];
    const float* W2 = (const float*)d_in[4];
    const float* b2 = (const float*)d_in[5];
    const float* Wc = (const float*)d_in[6];
    const float* bc = (const float*)d_in[7];
    float* out = (float*)d_out;

    const int E = in_sizes[1] / 2;

    constexpr int SMEM1 = 2 * (2 * 64 + 2 * H1) * 64;  // 49152
    constexpr int SMEM2 = 2 * (2 * 64 + 2 * H2) * 64;  // 32768

    static __half *p_hs1 = nullptr, *p_hs2 = nullptr;
    static float *p_acc1 = nullptr;
    static __nv_bfloat16 *p_w1h = nullptr, *p_w1l = nullptr, *p_w2h = nullptr, *p_w2l = nullptr;
    static cudaStream_t sideStream = nullptr;
    static cudaEvent_t evFork = nullptr, evJoin = nullptr;
    if (!p_hs1) {
        cudaGetSymbolAddress((void**)&p_hs1,  g_hs1);
        cudaGetSymbolAddress((void**)&p_acc1, g_acc1);
        cudaGetSymbolAddress((void**)&p_hs2,  g_hs2);
        cudaGetSymbolAddress((void**)&p_w1h,  g_W1t_hi);
        cudaGetSymbolAddress((void**)&p_w1l,  g_W1t_lo);
        cudaGetSymbolAddress((void**)&p_w2h,  g_W2t_hi);
        cudaGetSymbolAddress((void**)&p_w2l,  g_W2t_lo);
        cudaFuncSetAttribute(k_mm<64, H1, FIN, K1PAD, 3, 1>,
                             cudaFuncAttributeMaxDynamicSharedMemorySize, SMEM1);
        cudaFuncSetAttribute(k_mm<64, H2, H1, H1, 4, 1>,
                             cudaFuncAttributeMaxDynamicSharedMemorySize, SMEM2);
        cudaStreamCreateWithFlags(&sideStream, cudaStreamNonBlocking);
        cudaEventCreateWithFlags(&evFork, cudaEventDisableTiming);
        cudaEventCreateWithFlags(&evJoin, cudaEventDisableTiming);
    }

    const int grid = (NNODES + 63) / 64;   // 1563
    const int gridAgg = (NNODES + 7) / 8;  // 12500

    // 1: probe + zero hist + weight split
    k_probe_prep<<<512, 256>>>((const unsigned*)ei, W1, W2);
    // 2: degree histogram
    k_degree<<<(E + 255) / 256, 256>>>(ei, E);
    // 3: block sums + dis
    k_scanA<<<NB, 256>>>();
    // fork: CSR build runs on side stream, concurrent with layer-1 GEMM
    cudaEventRecord(evFork, 0);
    // 4: layer-1 GEMM on main stream (ncu -s 5 -c 1 window)
    k_mm<64, H1, FIN, K1PAD, 3, 1><<<grid, 256, SMEM1>>>(x, p_w1h, p_w1l, p_hs1, NNODES);
    cudaStreamWaitEvent(sideStream, evFork, 0);
    k_scanB<<<1, 512, 0, sideStream>>>();
    k_scanC<<<NB, 256, 0, sideStream>>>();
    k_fill<<<(E + 255) / 256, 256, 0, sideStream>>>(ei, E);
    cudaEventRecord(evJoin, sideStream);
    cudaStreamWaitEvent(0, evJoin, 0);
    // 8: layer-1 aggregation + relu (writes h into acc1, fp32)
    k_agg1<<<gridAgg, 256>>>(b1);
    // 9: layer-2 GEMM (fp32 in, fp16 out)
    k_mm<64, H2, H1, H1, 4, 1><<<grid, 256, SMEM2>>>(p_acc1, p_w2h, p_w2l, p_hs2, NNODES);
    // 10: layer-2 aggregation + relu + classifier
    k_agg2<<<gridAgg, 256>>>(b2, Wc, bc, out);
}

// round 15
// speedup vs baseline: 1.2038x; 1.1493x over previous
#include <cuda_runtime.h>
#include <cuda_fp16.h>
#include <cstdint>

// Problem constants (fixed by the dataset)
#define NNODES 100000
#define FIN    500
#define H1     128
#define H2     64
#define NC     10
#define K1PAD  512
#define EMAX   1700000
#define NB     391          // ceil(NNODES/256)

// ---------------- scratch (device globals; no allocs allowed) ----------------
__device__ __align__(16) float  g_dis [NNODES];
__device__ __align__(16) __half g_hs1 [NNODES * H1];   // dis*(x@W1), fp16
__device__ __align__(16) __half g_h1  [NNODES * H1];   // layer-1 output h, fp16
__device__ __align__(16) __half g_hs2 [NNODES * H2];   // dis*(h@W2), fp16
__device__ __align__(16) __half g_W1t_hi[H1 * K1PAD];  // fp16 hi
__device__ __align__(16) __half g_W1t_lo[H1 * K1PAD];  // fp16 residual
__device__ __align__(16) __half g_W2t_hi[H2 * H1];
__device__ __align__(16) __half g_W2t_lo[H2 * H1];
__device__ int g_cnt   [NNODES];
__device__ int g_part  [512];
__device__ int g_rowptr[NNODES + 1];
__device__ int g_cursor[NNODES];
__device__ int g_col   [EMAX];
__device__ int g_is64;

__device__ __forceinline__ uint32_t smem_u32(const void* p) {
    uint32_t a;
    asm("{ .reg .u64 t; cvta.to.shared.u64 t, %1; cvt.u32.u64 %0, t; }" : "=r"(a) : "l"(p));
    return a;
}
__device__ __forceinline__ void ldm_x4(uint32_t* r, uint32_t addr) {
    asm volatile("ldmatrix.sync.aligned.m8n8.x4.shared.b16 {%0,%1,%2,%3}, [%4];"
        : "=r"(r[0]), "=r"(r[1]), "=r"(r[2]), "=r"(r[3]) : "r"(addr));
}
__device__ __forceinline__ void mma_f16(float* c, const uint32_t* a, const uint32_t* b) {
    asm volatile("mma.sync.aligned.m16n8k16.row.col.f32.f16.f16.f32 "
        "{%0,%1,%2,%3}, {%4,%5,%6,%7}, {%8,%9}, {%0,%1,%2,%3};"
        : "+f"(c[0]), "+f"(c[1]), "+f"(c[2]), "+f"(c[3])
        : "r"(a[0]), "r"(a[1]), "r"(a[2]), "r"(a[3]), "r"(b[0]), "r"(b[1]));
}
__device__ __forceinline__ void cp16(uint32_t dst, const void* src) {
    asm volatile("cp.async.cg.shared.global [%0], [%1], 16;" :: "r"(dst), "l"(src));
}
__device__ __forceinline__ int eidx(const void* __restrict__ ei, long pos) {
    if (g_is64) return (int)((const long long*)ei)[pos];
    return ((const int*)ei)[pos];
}
// unit-level XOR swizzle: row r (64B = 4 units of 16B), unit u -> byte offset.
__device__ __forceinline__ uint32_t swz(int r, int u) {
    return (uint32_t)(((r * 4 + u) ^ (r & 7)) << 4);
}
// pack two fp32 -> fp16x2 (lo in low half)
__device__ __forceinline__ unsigned cvt_f16x2(float hi, float lo) {
    unsigned r;
    asm("cvt.rn.f16x2.f32 %0, %1, %2;" : "=r"(r) : "f"(hi), "f"(lo));
    return r;
}
// unpack 4 fp16 (uint2) -> float4
__device__ __forceinline__ float4 h2f4(uint2 v) {
    __half2 a = *reinterpret_cast<__half2*>(&v.x);
    __half2 b = *reinterpret_cast<__half2*>(&v.y);
    float2 fa = __half22float2(a), fb = __half22float2(b);
    return make_float4(fa.x, fa.y, fb.x, fb.y);
}
__device__ __forceinline__ float2 h2f2(unsigned v) {
    __half2 a = *reinterpret_cast<__half2*>(&v);
    return __half22float2(a);
}

// ---------- launch 1: probe dtype + zero histogram + weight split ------------
__global__ void k_probe_prep(const unsigned* __restrict__ w,
                             const float* __restrict__ W1,
                             const float* __restrict__ W2) {
    if (blockIdx.x == 0) {
        __shared__ unsigned red[256];
        unsigned o = 0;
        for (int i = threadIdx.x; i < 1024; i += 256) o |= w[2 * i + 1];
        red[threadIdx.x] = o;
        __syncthreads();
        for (int s = 128; s; s >>= 1) {
            if (threadIdx.x < s) red[threadIdx.x] |= red[threadIdx.x + s];
            __syncthreads();
        }
        if (threadIdx.x == 0) g_is64 = (red[0] == 0u) ? 1 : 0;
    }
    int i = blockIdx.x * blockDim.x + threadIdx.x;
    int stride = gridDim.x * blockDim.x;
    for (int j = i; j < NNODES; j += stride) g_cnt[j] = 0;
    for (int j = i; j < H1 * K1PAD; j += stride) {
        int n = j / K1PAD, k = j % K1PAD;
        float v = (k < FIN) ? W1[(long)k * H1 + n] : 0.f;
        __half h = __float2half_rn(v);
        g_W1t_hi[j] = h;
        g_W1t_lo[j] = __float2half_rn(v - __half2float(h));
    }
    for (int j = i; j < H2 * H1; j += stride) {
        int n = j / H1, k = j % H1;
        float v = W2[(long)k * H2 + n];
        __half h = __float2half_rn(v);
        g_W2t_hi[j] = h;
        g_W2t_lo[j] = __float2half_rn(v - __half2float(h));
    }
}

// ---------- launch 2: degree histogram --------------------------------------
__global__ void k_degree(const void* __restrict__ ei, int E) {
    int i = blockIdx.x * blockDim.x + threadIdx.x;
    if (i < E) atomicAdd(&g_cnt[eidx(ei, (long)E + i)], 1);
}

// ---------- launch 3: block sums + dis = rsqrt(cnt+1) ------------------------
__global__ void k_scanA() {
    int i = blockIdx.x * 256 + threadIdx.x;
    int v = (i < NNODES) ? g_cnt[i] : 0;
    if (i < NNODES) g_dis[i] = rsqrtf((float)v + 1.0f);
    __shared__ int s[256];
    s[threadIdx.x] = v;
    __syncthreads();
    for (int o = 128; o; o >>= 1) {
        if (threadIdx.x < o) s[threadIdx.x] += s[threadIdx.x + o];
        __syncthreads();
    }
    if (threadIdx.x == 0) g_part[blockIdx.x] = s[0];
}

// ---------- side stream: scan the 391 block partials (exclusive) -------------
__global__ void k_scanB() {
    __shared__ int s[512];
    int t = threadIdx.x;
    int v = (t < NB) ? g_part[t] : 0;
    s[t] = v;
    __syncthreads();
    for (int o = 1; o < 512; o <<= 1) {
        int x = (t >= o) ? s[t - o] : 0;
        __syncthreads();
        s[t] += x;
        __syncthreads();
    }
    if (t < NB) g_part[t] = s[t] - v;
}

// ---------- side stream: per-element exclusive scan -> rowptr + cursor -------
__global__ void k_scanC() {
    int b = blockIdx.x, t = threadIdx.x, i = b * 256 + t;
    int v = (i < NNODES) ? g_cnt[i] : 0;
    __shared__ int s[256];
    s[t] = v;
    __syncthreads();
    for (int o = 1; o < 256; o <<= 1) {
        int x = (t >= o) ? s[t - o] : 0;
        __syncthreads();
        s[t] += x;
        __syncthreads();
    }
    int excl = g_part[b] + s[t] - v;
    if (i < NNODES) {
        g_rowptr[i] = excl;
        g_cursor[i] = excl;
        if (i == NNODES - 1) g_rowptr[NNODES] = excl + v;
    }
}

// ---------- side stream: CSR fill (col = src grouped by dst) -----------------
__global__ void k_fill(const void* __restrict__ ei, int E) {
    int i = blockIdx.x * blockDim.x + threadIdx.x;
    if (i < E) {
        int s = eidx(ei, i);
        int d = eidx(ei, (long)E + i);
        int pos = atomicAdd(&g_cursor[d], 1);
        g_col[pos] = s;
    }
}

// ---------------- HMMA fp16 GEMM: Cout(fp16) = dis[row] * (A @ Bt^T) ---------
// A single fp16 (from fp32 convert or direct fp16), B fp16 hi+residual split
// -> 2 MMAs per tile-pair. BM=64, NCTA CTAs/SM, double-buffered XOR-swizzled
// SMEM (64B rows), cp.async for B (and A when A16=1).
template <int BM, int BN, int KREAL, int KPAD, int NCTA, int A16>
__global__ __launch_bounds__(256, NCTA) void k_mm(
    const void* __restrict__ Ain, const __half* __restrict__ Bh,
    const __half* __restrict__ Bl, __half* __restrict__ Cout, int M)
{
    constexpr int BK = 32, C = KPAD / BK;
    static_assert(C % 2 == 0, "C must be even");
    constexpr int WN = BN / 4;
    constexpr int NT = WN / 8;
    constexpr int MT = BM / 32;               // 2
    constexpr int STG = (BM + 2 * BN) * 64;
    constexpr uint32_t oBh = BM * 64;
    constexpr uint32_t oBl = BM * 64 + BN * 64;

    extern __shared__ char sm[];
    const uint32_t u0 = smem_u32(sm);

    const int tid = threadIdx.x, wid = tid >> 5, lane = tid & 31;
    const int wm = wid >> 2, wn = wid & 3;
    const int rowBase = blockIdx.x * BM;

    float acc[MT][NT][4];
    #pragma unroll
    for (int m = 0; m < MT; m++)
        #pragma unroll
        for (int n = 0; n < NT; n++)
            #pragma unroll
            for (int j = 0; j < 4; j++) acc[m][n][j] = 0.f;

    float4 aReg[2];
    const int aRow = tid >> 2;        // 4 threads per row
    const int uA   = tid & 3;         // one 16B unit per thread

    // fp32 A path: load 8 floats -> convert to 8 fp16 -> one swizzled STS.128
    auto loadA = [&](int c) {
        const int k0 = c * BK;
        const int grow = rowBase + aRow;
        const float* A = (const float*)Ain;
        #pragma unroll
        for (int i = 0; i < 2; i++) {
            int gcol = k0 + uA * 8 + i * 4;
            float4 v = make_float4(0.f, 0.f, 0.f, 0.f);
            if (grow < M) {
                if (gcol + 4 <= KREAL) {
                    v = *reinterpret_cast<const float4*>(A + (long)grow * KREAL + gcol);
                } else if (gcol < KREAL) {
                    float t[4];
                    #pragma unroll
                    for (int u = 0; u < 4; u++)
                        t[u] = (gcol + u < KREAL) ? A[(long)grow * KREAL + gcol + u] : 0.f;
                    v = make_float4(t[0], t[1], t[2], t[3]);
                }
            }
            aReg[i] = v;
        }
    };
    auto storeA = [&](int s) {
        unsigned h[4];
        #pragma unroll
        for (int i = 0; i < 2; i++) {
            float4 v = aReg[i];
            h[2 * i + 0] = cvt_f16x2(v.y, v.x);
            h[2 * i + 1] = cvt_f16x2(v.w, v.z);
        }
        *reinterpret_cast<uint4*>(sm + s * STG + swz(aRow, uA)) =
            make_uint4(h[0], h[1], h[2], h[3]);
    };
    // fp16 A path: direct cp.async (1 unit per thread; BM*4 == 256)
    auto cpA = [&](int c, int s) {
        int row = tid >> 2, u = tid & 3;
        int grow = rowBase + row;
        if (grow < M) {
            const char* src = (const char*)Ain + (long)grow * (KREAL * 2) +
                              (long)c * 64 + u * 16;
            cp16(u0 + s * STG + swz(row, u), src);
        }
    };
    auto cpB = [&](int c, int s) {
        #pragma unroll
        for (int i = tid; i < BN * 8; i += 256) {
            int mat = (i >= BN * 4) ? 1 : 0;
            int j = i - mat * BN * 4;
            int row = j >> 2, u = j & 3;
            const char* src = (const char*)(mat ? Bl : Bh) +
                              (long)row * (KPAD * 2) + (long)c * 64 + u * 16;
            uint32_t dst = u0 + s * STG + (mat ? oBl : oBh) + swz(row, u);
            cp16(dst, src);
        }
    };

    const int lRow = ((lane >> 3) & 1) * 8 + (lane & 7);
    const int uK   = lane >> 4;       // k-half unit offset

    auto compute = [&](int s) {   // literal s -> addresses fold
        const uint32_t base = u0 + s * STG;
        #pragma unroll
        for (int kk = 0; kk < 2; kk++) {
            uint32_t bfH[NT][2], bfL[NT][2];
            #pragma unroll
            for (int np = 0; np < NT / 2; np++) {
                int Rb = wn * WN + np * 16 + lRow;
                uint32_t off = base + oBh + swz(Rb, kk * 2 + uK);
                uint32_t rH[4], rL[4];
                ldm_x4(rH, off);
                ldm_x4(rL, off + (oBl - oBh));
                bfH[np * 2][0] = rH[0]; bfH[np * 2][1] = rH[2];
                bfH[np * 2 + 1][0] = rH[1]; bfH[np * 2 + 1][1] = rH[3];
                bfL[np * 2][0] = rL[0]; bfL[np * 2][1] = rL[2];
                bfL[np * 2 + 1][0] = rL[1]; bfL[np * 2 + 1][1] = rL[3];
            }
            #pragma unroll
            for (int mt = 0; mt < MT; mt++) {
                int Ra = wm * (MT * 16) + mt * 16 + lRow;
                uint32_t off = base + swz(Ra, kk * 2 + uK);
                uint32_t af[4];
                ldm_x4(af, off);
                #pragma unroll
                for (int nt = 0; nt < NT; nt++) {
                    mma_f16(acc[mt][nt], af, bfH[nt]);
                    mma_f16(acc[mt][nt], af, bfL[nt]);
                }
            }
        }
    };

    // prologue: chunk 0 into stage 0
    if (A16) {
        cpA(0, 0);
        cpB(0, 0);
    } else {
        loadA(0);
        cpB(0, 0);
        storeA(0);
    }
    asm volatile("cp.async.commit_group;");
    asm volatile("cp.async.wait_group 0;");
    __syncthreads();

    // main loop unrolled x2: stage indices are literals
    #pragma unroll 1
    for (int c = 0; c < C; c += 2) {
        const bool has1 = (c + 1 < C);
        const bool has2 = (c + 2 < C);
        if (has1) {
            if (A16) cpA(c + 1, 1); else loadA(c + 1);
            cpB(c + 1, 1);
            asm volatile("cp.async.commit_group;");
        }
        compute(0);
        if (has1) {
            if (!A16) storeA(1);
            asm volatile("cp.async.wait_group 0;");
            __syncthreads();
        }
        if (has2) {
            if (A16) cpA(c + 2, 0); else loadA(c + 2);
            cpB(c + 2, 0);
            asm volatile("cp.async.commit_group;");
        }
        if (has1) compute(1);
        if (has2) {
            if (!A16) storeA(0);
            asm volatile("cp.async.wait_group 0;");
            __syncthreads();
        }
    }

    // epilogue: scale rows by g_dis, store fp16
    #pragma unroll
    for (int mt = 0; mt < MT; mt++) {
        int r0 = rowBase + wm * (MT * 16) + mt * 16 + (lane >> 2);
        int r1 = r0 + 8;
        float s0 = (r0 < M) ? g_dis[r0] : 0.f;
        float s1 = (r1 < M) ? g_dis[r1] : 0.f;
        #pragma unroll
        for (int nt = 0; nt < NT; nt++) {
            int col = wn * WN + nt * 8 + 2 * (lane & 3);
            if (r0 < M) {
                unsigned hv = cvt_f16x2(acc[mt][nt][1] * s0, acc[mt][nt][0] * s0);
                *reinterpret_cast<unsigned*>(Cout + (long)r0 * BN + col) = hv;
            }
            if (r1 < M) {
                unsigned hv = cvt_f16x2(acc[mt][nt][3] * s1, acc[mt][nt][2] * s1);
                *reinterpret_cast<unsigned*>(Cout + (long)r1 * BN + col) = hv;
            }
        }
    }
}

// ---------- CSR aggregation layer1 + finish: warp = node, lane = 4 fp16 ------
__global__ __launch_bounds__(256) void k_agg1(const float* __restrict__ b1) {
    const int wid = threadIdx.x >> 5, lane = threadIdx.x & 31;
    const int n = blockIdx.x * 8 + wid;
    if (n >= NNODES) return;
    const int s0 = g_rowptr[n], e0 = g_rowptr[n + 1];
    const uint2* __restrict__ hs = reinterpret_cast<const uint2*>(g_hs1);  // 32 uint2/row
    float4 a0 = make_float4(0.f, 0.f, 0.f, 0.f), a1 = a0, a2 = a0, a3 = a0;
    int i = s0;
    for (; i + 4 <= e0; i += 4) {
        int c0 = g_col[i], c1 = g_col[i + 1], c2 = g_col[i + 2], c3 = g_col[i + 3];
        float4 v0 = h2f4(hs[(long)c0 * 32 + lane]);
        float4 v1 = h2f4(hs[(long)c1 * 32 + lane]);
        float4 v2 = h2f4(hs[(long)c2 * 32 + lane]);
        float4 v3 = h2f4(hs[(long)c3 * 32 + lane]);
        a0.x += v0.x; a0.y += v0.y; a0.z += v0.z; a0.w += v0.w;
        a1.x += v1.x; a1.y += v1.y; a1.z += v1.z; a1.w += v1.w;
        a2.x += v2.x; a2.y += v2.y; a2.z += v2.z; a2.w += v2.w;
        a3.x += v3.x; a3.y += v3.y; a3.z += v3.z; a3.w += v3.w;
    }
    for (; i < e0; i++) {
        float4 v = h2f4(hs[(long)g_col[i] * 32 + lane]);
        a0.x += v.x; a0.y += v.y; a0.z += v.z; a0.w += v.w;
    }
    float4 a = make_float4((a0.x + a1.x) + (a2.x + a3.x), (a0.y + a1.y) + (a2.y + a3.y),
                           (a0.z + a1.z) + (a2.z + a3.z), (a0.w + a1.w) + (a2.w + a3.w));
    float s = g_dis[n];
    float4 self = h2f4(hs[(long)n * 32 + lane]);
    float4 bb = __ldg(reinterpret_cast<const float4*>(b1) + lane);
    float rx = fmaxf(s * (a.x + self.x) + bb.x, 0.f);
    float ry = fmaxf(s * (a.y + self.y) + bb.y, 0.f);
    float rz = fmaxf(s * (a.z + self.z) + bb.z, 0.f);
    float rw = fmaxf(s * (a.w + self.w) + bb.w, 0.f);
    uint2 o;
    o.x = cvt_f16x2(ry, rx);
    o.y = cvt_f16x2(rw, rz);
    reinterpret_cast<uint2*>(g_h1)[(long)n * 32 + lane] = o;
}

// ---------- CSR aggregation layer2 + finish + classifier: warp = node --------
__global__ __launch_bounds__(256) void k_agg2(
    const float* __restrict__ b2, const float* __restrict__ Wc,
    const float* __restrict__ bc, float* __restrict__ out) {
    const int wid = threadIdx.x >> 5, lane = threadIdx.x & 31;
    const int n = blockIdx.x * 8 + wid;
    if (n >= NNODES) return;
    const int s0 = g_rowptr[n], e0 = g_rowptr[n + 1];
    const unsigned* __restrict__ hs = reinterpret_cast<const unsigned*>(g_hs2); // 32 half2/row
    float2 a0 = make_float2(0.f, 0.f), a1 = a0, a2 = a0, a3 = a0;
    int i = s0;
    for (; i + 4 <= e0; i += 4) {
        int c0 = g_col[i], c1 = g_col[i + 1], c2 = g_col[i + 2], c3 = g_col[i + 3];
        float2 v0 = h2f2(hs[(long)c0 * 32 + lane]);
        float2 v1 = h2f2(hs[(long)c1 * 32 + lane]);
        float2 v2 = h2f2(hs[(long)c2 * 32 + lane]);
        float2 v3 = h2f2(hs[(long)c3 * 32 + lane]);
        a0.x += v0.x; a0.y += v0.y;
        a1.x += v1.x; a1.y += v1.y;
        a2.x += v2.x; a2.y += v2.y;
        a3.x += v3.x; a3.y += v3.y;
    }
    for (; i < e0; i++) {
        float2 v = h2f2(hs[(long)g_col[i] * 32 + lane]);
        a0.x += v.x; a0.y += v.y;
    }
    float ax = (a0.x + a1.x) + (a2.x + a3.x);
    float ay = (a0.y + a1.y) + (a2.y + a3.y);
    float s = g_dis[n];
    float2 self = h2f2(hs[(long)n * 32 + lane]);
    float2 bb = __ldg(reinterpret_cast<const float2*>(b2) + lane);
    float hx = fmaxf(s * (ax + self.x) + bb.x, 0.f);
    float hy = fmaxf(s * (ay + self.y) + bb.y, 0.f);

    float p[NC];
    #pragma unroll
    for (int c = 0; c < NC; c++) {
        float v = hx * __ldg(&Wc[(2 * lane) * NC + c]) + hy * __ldg(&Wc[(2 * lane + 1) * NC + c]);
        #pragma unroll
        for (int o = 16; o; o >>= 1) v += __shfl_xor_sync(0xFFFFFFFFu, v, o);
        p[c] = v;
    }
    if (lane < NC) out[(long)n * NC + lane] = p[lane] + __ldg(&bc[lane]);
}

// ---------------- launch ------------------------------------------------------
extern "C" void kernel_launch(void* const* d_in, const int* in_sizes, int n_in,
                              void* d_out, int out_size)
{
    const float* x  = (const float*)d_in[0];
    const void*  ei = d_in[1];
    const float* W1 = (const float*)d_in[2];
    const float* b1 = (const float*)d_in[3];
    const float* W2 = (const float*)d_in[4];
    const float* b2 = (const float*)d_in[5];
    const float* Wc = (const float*)d_in[6];
    const float* bc = (const float*)d_in[7];
    float* out = (float*)d_out;

    const int E = in_sizes[1] / 2;

    constexpr int SMEM1 = 2 * (64 + 2 * H1) * 64;  // 40960
    constexpr int SMEM2 = 2 * (64 + 2 * H2) * 64;  // 24576

    static __half *p_hs1 = nullptr, *p_h1 = nullptr, *p_hs2 = nullptr;
    static __half *p_w1h = nullptr, *p_w1l = nullptr, *p_w2h = nullptr, *p_w2l = nullptr;
    static cudaStream_t sideStream = nullptr;
    static cudaEvent_t evFork = nullptr, evJoin = nullptr;
    if (!p_hs1) {
        cudaGetSymbolAddress((void**)&p_hs1, g_hs1);
        cudaGetSymbolAddress((void**)&p_h1,  g_h1);
        cudaGetSymbolAddress((void**)&p_hs2, g_hs2);
        cudaGetSymbolAddress((void**)&p_w1h, g_W1t_hi);
        cudaGetSymbolAddress((void**)&p_w1l, g_W1t_lo);
        cudaGetSymbolAddress((void**)&p_w2h, g_W2t_hi);
        cudaGetSymbolAddress((void**)&p_w2l, g_W2t_lo);
        cudaFuncSetAttribute(k_mm<64, H1, FIN, K1PAD, 3, 0>,
                             cudaFuncAttributeMaxDynamicSharedMemorySize, SMEM1);
        cudaFuncSetAttribute(k_mm<64, H2, H1, H1, 4, 1>,
                             cudaFuncAttributeMaxDynamicSharedMemorySize, SMEM2);
        cudaStreamCreateWithFlags(&sideStream, cudaStreamNonBlocking);
        cudaEventCreateWithFlags(&evFork, cudaEventDisableTiming);
        cudaEventCreateWithFlags(&evJoin, cudaEventDisableTiming);
    }

    const int grid = (NNODES + 63) / 64;   // 1563
    const int gridAgg = (NNODES + 7) / 8;  // 12500

    // 1: probe + zero hist + weight split
    k_probe_prep<<<512, 256>>>((const unsigned*)ei, W1, W2);
    // 2: degree histogram
    k_degree<<<(E + 255) / 256, 256>>>(ei, E);
    // 3: block sums + dis
    k_scanA<<<NB, 256>>>();
    // fork: CSR build runs on side stream, concurrent with layer-1 GEMM
    cudaEventRecord(evFork, 0);
    // 4: layer-1 GEMM on main stream (ncu -s 5 -c 1 window)
    k_mm<64, H1, FIN, K1PAD, 3, 0><<<grid, 256, SMEM1>>>(x, p_w1h, p_w1l, p_hs1, NNODES);
    cudaStreamWaitEvent(sideStream, evFork, 0);
    k_scanB<<<1, 512, 0, sideStream>>>();
    k_scanC<<<NB, 256, 0, sideStream>>>();
    k_fill<<<(E + 255) / 256, 256, 0, sideStream>>>(ei, E);
    cudaEventRecord(evJoin, sideStream);
    cudaStreamWaitEvent(0, evJoin, 0);
    // 8: layer-1 aggregation + relu (writes h into g_h1, fp16)
    k_agg1<<<gridAgg, 256>>>(b1);
    // 9: layer-2 GEMM (fp16 in via cp.async, fp16 out)
    k_mm<64, H2, H1, H1, 4, 1><<<grid, 256, SMEM2>>>(p_h1, p_w2h, p_w2l, p_hs2, NNODES);
    // 10: layer-2 aggregation + relu + classifier
    k_agg2<<<gridAgg, 256>>>(b2, Wc, bc, out);
}